// round 7
// baseline (speedup 1.0000x reference)
#include <cuda_runtime.h>
#include <cstdint>

// CSpace resonator bank as 1st-order complex IIR — single-pass decoupled-lookback scan.
// 1024 sequences x 25 slices (1920 samples); warp per slice.
// Phase A: slice affine total; publish aggregate; lookback -> entry; publish inclusive;
// Phase B: replay with outputs.

#define TT 48000
#define CC 64
#define BB 8
#define KLEN 24000
#define NSLICE 25
#define SLEN 1920
#define NITERS 15            // 15 * 128 = 1920
#define NSEQ (BB * CC * 2)   // 1024
#define NWORK (NSEQ * NSLICE)
#define WPB 8
#define NBLK (NWORK / WPB)   // 3200

// self-describing publish words: hi32 = float bits, lo32 = tag = epoch*4 + status
// status: 1 = aggregate (A_j), 2 = inclusive (P_j)
__device__ unsigned long long g_w1[NWORK];  // real part
__device__ unsigned long long g_w2[NWORK];  // imag part
__device__ float g_ctab[CC][24];
__device__ unsigned int g_ticket;
__device__ unsigned int g_epoch;

__device__ __forceinline__ void cmulD(double& ar, double& ai, double br, double bi) {
    double t = ar * br - ai * bi;
    ai = ar * bi + ai * br;
    ar = t;
}

__global__ void kprep(const float* __restrict__ kre, const float* __restrict__ kim) {
    int c = threadIdx.x;
    if (c == 0) { g_ticket = 0; g_epoch = g_epoch + 1; }
    if (c >= CC) return;
    double k0r = kre[c * KLEN + 0], k0i = kim[c * KLEN + 0];
    double k1r = kre[c * KLEN + 1], k1i = kim[c * KLEN + 1];
    double den = k0r * k0r + k0i * k0i;
    // fast double reciprocal: float seed + 2 Newton steps
    double inv = (double)__frcp_rn((float)den);
    inv = inv * (2.0 - den * inv);
    inv = inv * (2.0 - den * inv);
    double er = (k1r * k0r + k1i * k0i) * inv;
    double ei = (k1i * k0r - k1r * k0i) * inv;

    double e2r = er, e2i = ei;  cmulD(e2r, e2i, er, ei);
    double e3r = e2r, e3i = e2i; cmulD(e3r, e3i, er, ei);
    double e4r = e2r, e4i = e2i; cmulD(e4r, e4i, e2r, e2i);

    double Ar[6], Ai[6];
    Ar[0] = e4r; Ai[0] = e4i;
    #pragma unroll
    for (int k = 1; k < 6; ++k) { Ar[k] = Ar[k-1]; Ai[k] = Ai[k-1]; cmulD(Ar[k], Ai[k], Ar[k-1], Ai[k-1]); }
    double Cr[4], Ci[4];
    Cr[0] = Ar[5]; Ci[0] = Ai[5];
    #pragma unroll
    for (int k = 1; k < 4; ++k) { Cr[k] = Cr[k-1]; Ci[k] = Ci[k-1]; cmulD(Cr[k], Ci[k], Cr[k-1], Ci[k-1]); }
    double Fr = Cr[0], Fi = Ci[0];
    cmulD(Fr, Fi, Cr[1], Ci[1]);
    cmulD(Fr, Fi, Cr[2], Ci[2]);
    cmulD(Fr, Fi, Cr[3], Ci[3]);

    float* t = g_ctab[c];
    t[0] = (float)er;  t[1] = (float)ei;
    t[2] = (float)e2r; t[3] = (float)e2i;
    t[4] = (float)e3r; t[5] = (float)e3i;
    t[6] = (float)e4r; t[7] = (float)e4i;
    #pragma unroll
    for (int k = 0; k < 5; ++k) { t[8 + 2*k] = (float)Ar[k]; t[9 + 2*k] = (float)Ai[k]; }
    t[18] = (float)Ar[5]; t[19] = (float)Ai[5];
    t[20] = (float)Fr;    t[21] = (float)Fi;
    t[22] = (float)k0r;   t[23] = (float)k0i;
}

__device__ __forceinline__ void publish(int W, unsigned tag, float vr, float vi) {
    unsigned long long w1 = ((unsigned long long)__float_as_uint(vr) << 32) | tag;
    unsigned long long w2 = ((unsigned long long)__float_as_uint(vi) << 32) | tag;
    __stcg(&g_w1[W], w1);
    __stcg(&g_w2[W], w2);
}

template <bool REV>
__device__ __forceinline__ void do_seq(const float* __restrict__ x,
                                       float* __restrict__ out_re,
                                       float* __restrict__ out_im,
                                       int W, int s, int j, int lane,
                                       const float* __restrict__ tb,
                                       unsigned ep)
{
    const unsigned FULL = 0xFFFFFFFFu;
    const float er  = tb[0],  eic = tb[1];
    const float e2r = tb[2],  e2i = tb[3];
    const float e3r = tb[4],  e3i = tb[5];
    const float e4r = tb[6],  e4i = tb[7];
    const float a0r = tb[8],  a0i = tb[9];
    const float a1r = tb[10], a1i = tb[11];
    const float a2r = tb[12], a2i = tb[13];
    const float a3r = tb[14], a3i = tb[15];
    const float a4r = tb[16], a4i = tb[17];
    const float e128r = tb[18], e128i = tb[19];
    const float f19r  = tb[20], f19i  = tb[21];
    const float gr = tb[22], gi = tb[23];

    // ---------- Phase A: slice total ----------
    // weight = E4^(31-lane)
    float wr = 1.f, wi = 0.f;
    {
        int p = 31 - lane;
        #pragma unroll
        for (int k = 0; k < 5; ++k)
            if ((p >> k) & 1) {
                float ar = tb[8 + 2*k], ai = tb[9 + 2*k];
                float nr = wr*ar - wi*ai, ni = wr*ai + wi*ar;
                wr = nr; wi = ni;
            }
    }
    float Xr = 0.f, Xi = 0.f;
    #pragma unroll 5
    for (int i = 0; i < NITERS; ++i) {
        int n0 = j * SLEN + i * 128 + lane * 4;
        float4 v = REV ? *reinterpret_cast<const float4*>(x + (TT - 4 - n0))
                       : *reinterpret_cast<const float4*>(x + n0);
        float x0, x1, x2, x3;
        if (!REV) { x0=v.x; x1=v.y; x2=v.z; x3=v.w; }
        else      { x0=v.w; x1=v.z; x2=v.y; x3=v.x; }

        float yr = gr*x0, yi = gi*x0, tr, ti;
        tr = er*yr - eic*yi + gr*x1; ti = er*yi + eic*yr + gi*x1; yr=tr; yi=ti;
        tr = er*yr - eic*yi + gr*x2; ti = er*yi + eic*yr + gi*x2; yr=tr; yi=ti;
        tr = er*yr - eic*yi + gr*x3; ti = er*yi + eic*yr + gi*x3; yr=tr; yi=ti;

        float sr = wr*yr - wi*yi;
        float si = wr*yi + wi*yr;
        #pragma unroll
        for (int d = 16; d >= 1; d >>= 1) {
            sr += __shfl_xor_sync(FULL, sr, d);
            si += __shfl_xor_sync(FULL, si, d);
        }
        float nXr = sr + e128r*Xr - e128i*Xi;
        float nXi = si + e128r*Xi + e128i*Xr;
        Xr = nXr; Xi = nXi;
    }

    // ---------- publish aggregate / lookback / publish inclusive ----------
    float inr = 0.f, ini = 0.f;   // entry state P_{j-1}
    if (j == 0) {
        if (lane == 0) publish(W, ep * 4u + 2u, Xr, Xi);  // inclusive directly
    } else {
        if (lane == 0) {
            publish(W, ep * 4u + 1u, Xr, Xi);             // aggregate
            const int base = s * NSLICE;
            const unsigned tagmin = ep * 4u + 1u;
            float fr = 1.f, fi = 0.f;                      // E1920^(j-1-t)
            int t = j - 1;
            while (t >= 0) {
                unsigned long long w1, w2;
                for (;;) {
                    w1 = __ldcg(&g_w1[base + t]);
                    w2 = __ldcg(&g_w2[base + t]);
                    unsigned t1 = (unsigned)w1;
                    if (t1 >= tagmin && t1 == (unsigned)w2) break;
                    __nanosleep(32);
                }
                float vr = __uint_as_float((unsigned)(w1 >> 32));
                float vi = __uint_as_float((unsigned)(w2 >> 32));
                inr += fr*vr - fi*vi;
                ini += fr*vi + fi*vr;
                if (((unsigned)w1 - ep * 4u) == 2u) break; // hit inclusive
                float nfr = fr*f19r - fi*f19i;
                float nfi = fr*f19i + fi*f19r;
                fr = nfr; fi = nfi;
                --t;
            }
            // inclusive for this slice: P_j = A_j + E1920 * entry
            if (j != NSLICE - 1) {
                float Pr = Xr + f19r*inr - f19i*ini;
                float Pi = Xi + f19r*ini + f19i*inr;
                publish(W, ep * 4u + 2u, Pr, Pi);
            }
        }
        inr = __shfl_sync(FULL, inr, 0);
        ini = __shfl_sync(FULL, ini, 0);
    }

    // ---------- Phase B: replay with outputs ----------
    // q = E4^lane
    float qr = 1.f, qi = 0.f;
    #pragma unroll
    for (int k = 0; k < 5; ++k)
        if ((lane >> k) & 1) {
            float ar = tb[8 + 2*k], ai = tb[9 + 2*k];
            float nr = qr*ar - qi*ai, ni = qr*ai + qi*ar;
            qr = nr; qi = ni;
        }

    #pragma unroll 3
    for (int i = 0; i < NITERS; ++i) {
        int n0 = j * SLEN + i * 128 + lane * 4;
        float4 v = REV ? *reinterpret_cast<const float4*>(x + (TT - 4 - n0))
                       : *reinterpret_cast<const float4*>(x + n0);
        float x0, x1, x2, x3;
        if (!REV) { x0=v.x; x1=v.y; x2=v.z; x3=v.w; }
        else      { x0=v.w; x1=v.z; x2=v.y; x3=v.x; }

        float c1r = gr*x0, c1i = gi*x0;
        float c2r = er*c1r - eic*c1i + gr*x1, c2i = er*c1i + eic*c1r + gi*x1;
        float c3r = er*c2r - eic*c2i + gr*x2, c3i = er*c2i + eic*c2r + gi*x2;
        float c4r = er*c3r - eic*c3i + gr*x3, c4i = er*c3i + eic*c3r + gi*x3;

        float sr = c4r, si = c4i;
        { float ur=__shfl_up_sync(FULL,sr,1),  ui=__shfl_up_sync(FULL,si,1);
          if (lane>=1)  { sr += a0r*ur - a0i*ui; si += a0r*ui + a0i*ur; } }
        { float ur=__shfl_up_sync(FULL,sr,2),  ui=__shfl_up_sync(FULL,si,2);
          if (lane>=2)  { sr += a1r*ur - a1i*ui; si += a1r*ui + a1i*ur; } }
        { float ur=__shfl_up_sync(FULL,sr,4),  ui=__shfl_up_sync(FULL,si,4);
          if (lane>=4)  { sr += a2r*ur - a2i*ui; si += a2r*ui + a2i*ur; } }
        { float ur=__shfl_up_sync(FULL,sr,8),  ui=__shfl_up_sync(FULL,si,8);
          if (lane>=8)  { sr += a3r*ur - a3i*ui; si += a3r*ui + a3i*ur; } }
        { float ur=__shfl_up_sync(FULL,sr,16), ui=__shfl_up_sync(FULL,si,16);
          if (lane>=16) { sr += a4r*ur - a4i*ui; si += a4r*ui + a4i*ur; } }

        float hr = __shfl_up_sync(FULL, sr, 1);
        float hi = __shfl_up_sync(FULL, si, 1);
        if (lane == 0) { hr = 0.f; hi = 0.f; }

        float zr = hr + qr*inr - qi*ini;
        float zi = hi + qr*ini + qi*inr;

        float o1r = c1r + er*zr  - eic*zi, o1i = c1i + er*zi  + eic*zr;
        float o2r = c2r + e2r*zr - e2i*zi, o2i = c2i + e2r*zi + e2i*zr;
        float o3r = c3r + e3r*zr - e3i*zi, o3i = c3i + e3r*zi + e3i*zr;
        float o4r = c4r + e4r*zr - e4i*zi, o4i = c4i + e4r*zi + e4i*zr;

        if (!REV) {
            *reinterpret_cast<float4*>(out_re + n0) = make_float4(o1r,o2r,o3r,o4r);
            *reinterpret_cast<float4*>(out_im + n0) = make_float4(o1i,o2i,o3i,o4i);
        } else {
            *reinterpret_cast<float4*>(out_re + (TT - 4 - n0)) = make_float4(o4r,o3r,o2r,o1r);
            *reinterpret_cast<float4*>(out_im + (TT - 4 - n0)) = make_float4(o4i,o3i,o2i,o1i);
        }

        float Tr = __shfl_sync(FULL, sr, 31);
        float Ti = __shfl_sync(FULL, si, 31);
        float nr = Tr + e128r*inr - e128i*ini;
        float ni = Ti + e128r*ini + e128i*inr;
        inr = nr; ini = ni;
    }
}

__global__ void __launch_bounds__(WPB * 32, 4)
kFused(const float* __restrict__ audio, float* __restrict__ out)
{
    __shared__ unsigned int s_bt;
    if (threadIdx.x == 0) s_bt = atomicAdd(&g_ticket, 1u);
    __syncthreads();
    unsigned ep = g_epoch;

    int W = (int)s_bt * WPB + (threadIdx.x >> 5);
    int lane = threadIdx.x & 31;
    int s = W / NSLICE;
    int j = W - s * NSLICE;
    int dir = s & 1, c = (s >> 1) & 63, b = s >> 7;

    const float* tb = g_ctab[c];
    const float* x = audio + (size_t)b * TT;
    float* base = out + (size_t)b * 4 * CC * TT;

    if (dir == 0) {
        do_seq<false>(x, base + (size_t)c * TT, base + (size_t)(CC + c) * TT,
                      W, s, j, lane, tb, ep);
    } else {
        do_seq<true >(x, base + (size_t)(2*CC + c) * TT, base + (size_t)(3*CC + c) * TT,
                      W, s, j, lane, tb, ep);
    }
}

extern "C" void kernel_launch(void* const* d_in, const int* in_sizes, int n_in,
                              void* d_out, int out_size)
{
    const float* audio = (const float*)d_in[0];
    const float* kre   = (const float*)d_in[1];
    const float* kim   = (const float*)d_in[2];
    float* out = (float*)d_out;
    (void)in_sizes; (void)n_in; (void)out_size;

    kprep<<<1, 64>>>(kre, kim);
    kFused<<<NBLK, WPB * 32>>>(audio, out);
}

// round 8
// speedup vs baseline: 1.5171x; 1.5171x over previous
#include <cuda_runtime.h>
#include <cstdint>

// CSpace resonator bank as 1st-order complex IIR, split-scan over time slices.
// 1024 sequences x 25 slices of 1920 samples; warp per slice.
// Kernel A: slice affine totals (deferred reduction, no per-iter shuffles).
// Kernel C: fold entry + replay with streaming-store outputs.

#define TT 48000
#define CC 64
#define BB 8
#define KLEN 24000
#define NSLICE 25
#define SLEN 1920
#define NITERS 15           // 15 * 128 = 1920
#define NSEQ (BB * CC * 2)  // 1024
#define NWORK (NSEQ * NSLICE) // 25600
#define WPB 8               // warps per block
#define NBLK (NWORK / WPB)  // 3200

__device__ float2 g_tot[NWORK];
// per-channel table: [0..7] e^1..e^4 (re,im), [8..17] A_k=E4^(2^k) k=0..4,
// [18..19] E128, [20..21] E1920, [22..23] g
__device__ float g_ctab[CC][24];

__device__ __forceinline__ void cmulD(double& ar, double& ai, double br, double bi) {
    double t = ar * br - ai * bi;
    ai = ar * bi + ai * br;
    ar = t;
}

__global__ void kprep(const float* __restrict__ kre, const float* __restrict__ kim) {
    int c = threadIdx.x;
    if (c >= CC) return;
    double k0r = kre[c * KLEN + 0], k0i = kim[c * KLEN + 0];
    double k1r = kre[c * KLEN + 1], k1i = kim[c * KLEN + 1];
    double inv = 1.0 / (k0r * k0r + k0i * k0i);
    double er = (k1r * k0r + k1i * k0i) * inv;
    double ei = (k1i * k0r - k1r * k0i) * inv;

    double e2r = er, e2i = ei;  cmulD(e2r, e2i, er, ei);
    double e3r = e2r, e3i = e2i; cmulD(e3r, e3i, er, ei);
    double e4r = e2r, e4i = e2i; cmulD(e4r, e4i, e2r, e2i);

    double Ar[6], Ai[6];
    Ar[0] = e4r; Ai[0] = e4i;
    #pragma unroll
    for (int k = 1; k < 6; ++k) { Ar[k] = Ar[k-1]; Ai[k] = Ai[k-1]; cmulD(Ar[k], Ai[k], Ar[k-1], Ai[k-1]); }
    double Cr[4], Ci[4];
    Cr[0] = Ar[5]; Ci[0] = Ai[5];
    #pragma unroll
    for (int k = 1; k < 4; ++k) { Cr[k] = Cr[k-1]; Ci[k] = Ci[k-1]; cmulD(Cr[k], Ci[k], Cr[k-1], Ci[k-1]); }
    double Fr = Cr[0], Fi = Ci[0];
    cmulD(Fr, Fi, Cr[1], Ci[1]);
    cmulD(Fr, Fi, Cr[2], Ci[2]);
    cmulD(Fr, Fi, Cr[3], Ci[3]);

    float* t = g_ctab[c];
    t[0] = (float)er;  t[1] = (float)ei;
    t[2] = (float)e2r; t[3] = (float)e2i;
    t[4] = (float)e3r; t[5] = (float)e3i;
    t[6] = (float)e4r; t[7] = (float)e4i;
    #pragma unroll
    for (int k = 0; k < 5; ++k) { t[8 + 2*k] = (float)Ar[k]; t[9 + 2*k] = (float)Ai[k]; }
    t[18] = (float)Ar[5]; t[19] = (float)Ai[5];
    t[20] = (float)Fr;    t[21] = (float)Fi;
    t[22] = (float)k0r;   t[23] = (float)k0i;
}

// ---------------- Kernel A: slice totals (deferred reduction) ----------------
template <bool REV>
__device__ __forceinline__ void sliceA(const float* __restrict__ x, int j, int lane,
                                       const float* __restrict__ tb, int W)
{
    const unsigned FULL = 0xFFFFFFFFu;
    const float er = tb[0], ei = tb[1];
    const float e128r = tb[18], e128i = tb[19];
    const float gr = tb[22], gi = tb[23];

    // lane-local accumulator: A = E128*A + y_i   (y_i = local 4-sample partial)
    float Acr = 0.f, Aci = 0.f;
    #pragma unroll 5
    for (int i = 0; i < NITERS; ++i) {
        int n0 = j * SLEN + i * 128 + lane * 4;
        float4 v = REV ? *reinterpret_cast<const float4*>(x + (TT - 4 - n0))
                       : *reinterpret_cast<const float4*>(x + n0);
        float x0, x1, x2, x3;
        if (!REV) { x0=v.x; x1=v.y; x2=v.z; x3=v.w; }
        else      { x0=v.w; x1=v.z; x2=v.y; x3=v.x; }

        float yr = gr*x0, yi = gi*x0, tr, ti;
        tr = er*yr - ei*yi + gr*x1; ti = er*yi + ei*yr + gi*x1; yr=tr; yi=ti;
        tr = er*yr - ei*yi + gr*x2; ti = er*yi + ei*yr + gi*x2; yr=tr; yi=ti;
        tr = er*yr - ei*yi + gr*x3; ti = er*yi + ei*yr + gi*x3; yr=tr; yi=ti;

        float nAr = yr + e128r*Acr - e128i*Aci;
        float nAi = yi + e128r*Aci + e128i*Acr;
        Acr = nAr; Aci = nAi;
    }

    // weight = E4^(31-lane); one butterfly reduction of w*A
    float wr = 1.f, wi = 0.f;
    {
        int p = 31 - lane;
        #pragma unroll
        for (int k = 0; k < 5; ++k)
            if ((p >> k) & 1) {
                float ar = tb[8 + 2*k], ai = tb[9 + 2*k];
                float nr = wr*ar - wi*ai, ni = wr*ai + wi*ar;
                wr = nr; wi = ni;
            }
    }
    float sr = wr*Acr - wi*Aci;
    float si = wr*Aci + wi*Acr;
    #pragma unroll
    for (int d = 16; d >= 1; d >>= 1) {
        sr += __shfl_xor_sync(FULL, sr, d);
        si += __shfl_xor_sync(FULL, si, d);
    }
    if (lane == 0) g_tot[W] = make_float2(sr, si);
}

__global__ void __launch_bounds__(WPB * 32)
kA(const float* __restrict__ audio)
{
    int lane = threadIdx.x & 31;
    int W = blockIdx.x * WPB + (threadIdx.x >> 5);
    int s = W / NSLICE;
    int j = W - s * NSLICE;
    int dir = s & 1, c = (s >> 1) & 63, b = s >> 7;

    const float* tb = g_ctab[c];
    const float* x = audio + (size_t)b * TT;
    if (dir == 0) sliceA<false>(x, j, lane, tb, W);
    else          sliceA<true >(x, j, lane, tb, W);
}

// ---------------- Kernel C: outputs ----------------
__device__ __forceinline__ void st_cs4(float* p, float4 v) {
    asm volatile("st.global.cs.v4.f32 [%0], {%1,%2,%3,%4};"
                 :: "l"(p), "f"(v.x), "f"(v.y), "f"(v.z), "f"(v.w) : "memory");
}

template <bool REV>
__device__ __forceinline__ void sliceC(const float* __restrict__ x,
                                       float* __restrict__ out_re,
                                       float* __restrict__ out_im,
                                       int s, int j, int lane,
                                       const float* __restrict__ tb)
{
    const unsigned FULL = 0xFFFFFFFFu;
    const float er  = tb[0],  eic = tb[1];
    const float e2r = tb[2],  e2i = tb[3];
    const float e3r = tb[4],  e3i = tb[5];
    const float e4r = tb[6],  e4i = tb[7];
    const float a0r = tb[8],  a0i = tb[9];
    const float a1r = tb[10], a1i = tb[11];
    const float a2r = tb[12], a2i = tb[13];
    const float a3r = tb[14], a3i = tb[15];
    const float a4r = tb[16], a4i = tb[17];
    const float e128r = tb[18], e128i = tb[19];
    const float f19r  = tb[20], f19i  = tb[21];
    const float gr = tb[22], gi = tb[23];

    // q = E4^lane
    float qr = 1.f, qi = 0.f;
    #pragma unroll
    for (int k = 0; k < 5; ++k)
        if ((lane >> k) & 1) {
            float ar = tb[8 + 2*k], ai = tb[9 + 2*k];
            float nr = qr*ar - qi*ai, ni = qr*ai + qi*ar;
            qr = nr; qi = ni;
        }

    // fold predecessor slice totals -> entry state (uniform loads, all lanes)
    float inr = 0.f, ini = 0.f;
    const float2* tot = &g_tot[s * NSLICE];
    for (int t = 0; t < j; ++t) {
        float2 v = tot[t];
        float nr = v.x + f19r*inr - f19i*ini;
        float ni = v.y + f19r*ini + f19i*inr;
        inr = nr; ini = ni;
    }

    #pragma unroll 3
    for (int i = 0; i < NITERS; ++i) {
        int n0 = j * SLEN + i * 128 + lane * 4;
        float4 v = REV ? *reinterpret_cast<const float4*>(x + (TT - 4 - n0))
                       : *reinterpret_cast<const float4*>(x + n0);
        float x0, x1, x2, x3;
        if (!REV) { x0=v.x; x1=v.y; x2=v.z; x3=v.w; }
        else      { x0=v.w; x1=v.z; x2=v.y; x3=v.x; }

        // local partials from zero (kept for output reconstruction)
        float c1r = gr*x0, c1i = gi*x0;
        float c2r = er*c1r - eic*c1i + gr*x1, c2i = er*c1i + eic*c1r + gi*x1;
        float c3r = er*c2r - eic*c2i + gr*x2, c3i = er*c2i + eic*c2r + gi*x2;
        float c4r = er*c3r - eic*c3i + gr*x3, c4i = er*c3i + eic*c3r + gi*x3;

        // warp inclusive scan of c4 with ratio E4
        float sr = c4r, si = c4i;
        { float ur=__shfl_up_sync(FULL,sr,1),  ui=__shfl_up_sync(FULL,si,1);
          if (lane>=1)  { sr += a0r*ur - a0i*ui; si += a0r*ui + a0i*ur; } }
        { float ur=__shfl_up_sync(FULL,sr,2),  ui=__shfl_up_sync(FULL,si,2);
          if (lane>=2)  { sr += a1r*ur - a1i*ui; si += a1r*ui + a1i*ur; } }
        { float ur=__shfl_up_sync(FULL,sr,4),  ui=__shfl_up_sync(FULL,si,4);
          if (lane>=4)  { sr += a2r*ur - a2i*ui; si += a2r*ui + a2i*ur; } }
        { float ur=__shfl_up_sync(FULL,sr,8),  ui=__shfl_up_sync(FULL,si,8);
          if (lane>=8)  { sr += a3r*ur - a3i*ui; si += a3r*ui + a3i*ur; } }
        { float ur=__shfl_up_sync(FULL,sr,16), ui=__shfl_up_sync(FULL,si,16);
          if (lane>=16) { sr += a4r*ur - a4i*ui; si += a4r*ui + a4i*ur; } }

        float hr = __shfl_up_sync(FULL, sr, 1);
        float hi = __shfl_up_sync(FULL, si, 1);
        if (lane == 0) { hr = 0.f; hi = 0.f; }

        // lane entry z = h + q*in
        float zr = hr + qr*inr - qi*ini;
        float zi = hi + qr*ini + qi*inr;

        // outputs o_k = c_k + e^k * z
        float o1r = c1r + er*zr  - eic*zi, o1i = c1i + er*zi  + eic*zr;
        float o2r = c2r + e2r*zr - e2i*zi, o2i = c2i + e2r*zi + e2i*zr;
        float o3r = c3r + e3r*zr - e3i*zi, o3i = c3i + e3r*zi + e3i*zr;
        float o4r = c4r + e4r*zr - e4i*zi, o4i = c4i + e4r*zi + e4i*zr;

        if (!REV) {
            st_cs4(out_re + n0, make_float4(o1r,o2r,o3r,o4r));
            st_cs4(out_im + n0, make_float4(o1i,o2i,o3i,o4i));
        } else {
            st_cs4(out_re + (TT - 4 - n0), make_float4(o4r,o3r,o2r,o1r));
            st_cs4(out_im + (TT - 4 - n0), make_float4(o4i,o3i,o2i,o1i));
        }

        // advance slice-entry state: in = T + E128*in  (T = inclusive total, lane 31)
        float Tr = __shfl_sync(FULL, sr, 31);
        float Ti = __shfl_sync(FULL, si, 31);
        float nr = Tr + e128r*inr - e128i*ini;
        float ni = Ti + e128r*ini + e128i*inr;
        inr = nr; ini = ni;
    }
}

__global__ void __launch_bounds__(WPB * 32)
kC(const float* __restrict__ audio, float* __restrict__ out)
{
    int lane = threadIdx.x & 31;
    int W = blockIdx.x * WPB + (threadIdx.x >> 5);
    int s = W / NSLICE;
    int j = W - s * NSLICE;
    int dir = s & 1, c = (s >> 1) & 63, b = s >> 7;

    const float* tb = g_ctab[c];
    const float* x = audio + (size_t)b * TT;
    float* base = out + (size_t)b * 4 * CC * TT;

    if (dir == 0) {
        sliceC<false>(x, base + (size_t)c * TT, base + (size_t)(CC + c) * TT,
                      s, j, lane, tb);
    } else {
        sliceC<true >(x, base + (size_t)(2*CC + c) * TT, base + (size_t)(3*CC + c) * TT,
                      s, j, lane, tb);
    }
}

extern "C" void kernel_launch(void* const* d_in, const int* in_sizes, int n_in,
                              void* d_out, int out_size)
{
    const float* audio = (const float*)d_in[0];
    const float* kre   = (const float*)d_in[1];
    const float* kim   = (const float*)d_in[2];
    float* out = (float*)d_out;
    (void)in_sizes; (void)n_in; (void)out_size;

    kprep<<<1, 64>>>(kre, kim);
    kA<<<NBLK, WPB * 32>>>(audio);
    kC<<<NBLK, WPB * 32>>>(audio, out);
}